// round 3
// baseline (speedup 1.0000x reference)
#include <cuda_runtime.h>
#include <cuda_bf16.h>
#include <cstdint>
#include <math.h>

#define EPS 1e-6f
#define B_  8
#define LQ  1024
#define LK  8192
#define D_  256
#define DC  128

// ---------------- scratch (device globals; no allocations allowed) ----------
__device__ __nv_bfloat16 g_qp[B_ * LQ * DC];   // q' = q @ W_up  (bf16)      2 MB
__device__ float         g_qsq[B_ * LQ];       // ||q||^2 (fp32)
__device__ __nv_bfloat16 g_kc[B_ * LK * DC];   // dequantized k_c (bf16)    16 MB
__device__ float         g_ksq[B_ * LK];       // ||k||^2 via Gram form
__device__ __nv_bfloat16 g_G[DC * DC];         // G = W^T W (bf16)

// ---------------- kernel 1: Gram matrix G = W^T W ---------------------------
__global__ void g_kernel(const float* __restrict__ W) {
    int c1 = blockIdx.x, c2 = threadIdx.x;
    float acc = 0.f;
#pragma unroll 8
    for (int d = 0; d < D_; ++d)
        acc = fmaf(__ldg(W + d * DC + c1), __ldg(W + d * DC + c2), acc);
    g_G[c1 * DC + c2] = __float2bfloat16(acc);
}

// ---------------- kernel 2: q' = q @ W_up (bf16) and q_sq -------------------
__global__ __launch_bounds__(256) void qp_kernel(const float* __restrict__ q,
                                                 const float* __restrict__ W) {
    __shared__ float qs[8 * 256];
    int t = threadIdx.x;
    size_t base = (size_t)blockIdx.x * 2048;  // 8 rows x 256
#pragma unroll
    for (int i = t; i < 2048; i += 256) qs[i] = q[base + i];
    __syncthreads();

    int lane = t & 31, w = t >> 5;
    // q_sq: warp w reduces row w
    float s = 0.f;
#pragma unroll
    for (int i = 0; i < 8; ++i) {
        float v = qs[w * 256 + lane + i * 32];
        s = fmaf(v, v, s);
    }
#pragma unroll
    for (int o = 16; o; o >>= 1) s += __shfl_xor_sync(0xffffffffu, s, o);
    if (lane == 0) g_qsq[blockIdx.x * 8 + w] = s;

    // q': thread (w, lane) computes cols 4*lane..4*lane+3 of row w
    const float4* W4 = (const float4*)W;
    float ax = 0.f, ay = 0.f, az = 0.f, aw = 0.f;
#pragma unroll 4
    for (int d = 0; d < D_; ++d) {
        float qv = qs[w * 256 + d];
        float4 ww = W4[d * 32 + lane];
        ax = fmaf(qv, ww.x, ax);
        ay = fmaf(qv, ww.y, ay);
        az = fmaf(qv, ww.z, az);
        aw = fmaf(qv, ww.w, aw);
    }
    __nv_bfloat162 p01 = __floats2bfloat162_rn(ax, ay);
    __nv_bfloat162 p23 = __floats2bfloat162_rn(az, aw);
    uint2 wv = make_uint2(*reinterpret_cast<unsigned int*>(&p01),
                          *reinterpret_cast<unsigned int*>(&p23));
    ((uint2*)g_qp)[(blockIdx.x * 8 + w) * 32 + lane] = wv;
}

// ---------------- kernel 3: int4-code dequant -> bf16 -----------------------
__global__ void deq_kernel(const int* __restrict__ kq,
                           const float* __restrict__ sc,
                           const float* __restrict__ zp) {
    int i = blockIdx.x * 256 + threadIdx.x;  // item of 4 elements
    int4 v = ((const int4*)kq)[i];
    int flat = i << 2;
    int c = flat & (DC - 1);
    int b = flat >> 20;  // 8192*128 = 2^20 elems per batch
    float4 s = *(const float4*)(sc + b * DC + c);
    float4 z = *(const float4*)(zp + b * DC + c);
    float f0 = s.x * ((float)v.x - z.x);
    float f1 = s.y * ((float)v.y - z.y);
    float f2 = s.z * ((float)v.z - z.z);
    float f3 = s.w * ((float)v.w - z.w);
    __nv_bfloat162 p01 = __floats2bfloat162_rn(f0, f1);
    __nv_bfloat162 p23 = __floats2bfloat162_rn(f2, f3);
    uint2 wv = make_uint2(*reinterpret_cast<unsigned int*>(&p01),
                          *reinterpret_cast<unsigned int*>(&p23));
    ((uint2*)g_kc)[i] = wv;
}

// ---------------- shared 128x128x128 bf16 block-MMA (mma.sync) --------------
// Tiles in smem with padded stride 136 bf16 (272 B) -> conflict-free ldmatrix.
// acc[mi][ni][e]: warp tile 32(M) x 64(N); warps 4(M) x 2(N).
__device__ __forceinline__ void block_mma_128(uint32_t smA, uint32_t smB,
                                              int lane, int warp_m, int warp_n,
                                              float acc[2][8][4]) {
    const int STRIDE = 272;
#pragma unroll
    for (int kk = 0; kk < 8; ++kk) {
        uint32_t a[2][4];
#pragma unroll
        for (int mi = 0; mi < 2; ++mi) {
            int row = warp_m * 32 + mi * 16 + (lane & 15);
            uint32_t addr = smA + row * STRIDE + kk * 32 + ((lane >> 4) << 4);
            asm volatile("ldmatrix.sync.aligned.m8n8.x4.shared.b16 {%0,%1,%2,%3}, [%4];"
                         : "=r"(a[mi][0]), "=r"(a[mi][1]), "=r"(a[mi][2]), "=r"(a[mi][3])
                         : "r"(addr));
        }
        uint32_t bb[8][2];
#pragma unroll
        for (int nn = 0; nn < 4; ++nn) {
            int nrow = warp_n * 64 + nn * 16 + (lane & 7) + (((lane >> 4) & 1) << 3);
            uint32_t addr = smB + nrow * STRIDE + kk * 32 + (((lane >> 3) & 1) << 4);
            uint32_t r0, r1, r2, r3;
            asm volatile("ldmatrix.sync.aligned.m8n8.x4.shared.b16 {%0,%1,%2,%3}, [%4];"
                         : "=r"(r0), "=r"(r1), "=r"(r2), "=r"(r3)
                         : "r"(addr));
            bb[2 * nn][0] = r0; bb[2 * nn][1] = r1;
            bb[2 * nn + 1][0] = r2; bb[2 * nn + 1][1] = r3;
        }
#pragma unroll
        for (int mi = 0; mi < 2; ++mi)
#pragma unroll
            for (int ni = 0; ni < 8; ++ni)
                asm volatile(
                    "mma.sync.aligned.m16n8k16.row.col.f32.bf16.bf16.f32 "
                    "{%0,%1,%2,%3}, {%4,%5,%6,%7}, {%8,%9}, {%0,%1,%2,%3};"
                    : "+f"(acc[mi][ni][0]), "+f"(acc[mi][ni][1]),
                      "+f"(acc[mi][ni][2]), "+f"(acc[mi][ni][3])
                    : "r"(a[mi][0]), "r"(a[mi][1]), "r"(a[mi][2]), "r"(a[mi][3]),
                      "r"(bb[ni][0]), "r"(bb[ni][1]));
    }
}

// ---------------- kernel 4: k_sq via Gram quadratic form --------------------
__global__ __launch_bounds__(256) void ksq_kernel() {
    extern __shared__ char smem[];
    __nv_bfloat16* smA = (__nv_bfloat16*)smem;             // kc tile 128x136
    float* s_acc = (float*)(smem + 69632);
    int t = threadIdx.x;
    int k0 = blockIdx.x * 128;  // flat row over B_*LK

    const uint4* gA = (const uint4*)(g_kc + (size_t)k0 * DC);
    const uint4* gB = (const uint4*)g_G;
    uint4* sA4 = (uint4*)smem;
    uint4* sB4 = (uint4*)(smem + 34816);
#pragma unroll
    for (int i = t; i < 2048; i += 256) {
        int r = i >> 4, ch = i & 15;
        sA4[r * 17 + ch] = gA[i];
        sB4[r * 17 + ch] = gB[i];
    }
    if (t < 128) s_acc[t] = 0.f;
    __syncthreads();

    int lane = t & 31, wid = t >> 5;
    int warp_m = wid & 3, warp_n = wid >> 2;
    float acc[2][8][4];
#pragma unroll
    for (int mi = 0; mi < 2; ++mi)
#pragma unroll
        for (int ni = 0; ni < 8; ++ni)
#pragma unroll
            for (int e = 0; e < 4; ++e) acc[mi][ni][e] = 0.f;

    uint32_t smA_u = (uint32_t)__cvta_generic_to_shared(smem);
    uint32_t smB_u = (uint32_t)__cvta_generic_to_shared(smem + 34816);
    block_mma_128(smA_u, smB_u, lane, warp_m, warp_n, acc);

    int g = lane >> 2, tg = lane & 3;
#pragma unroll
    for (int mi = 0; mi < 2; ++mi)
#pragma unroll
        for (int h = 0; h < 2; ++h) {
            int row = warp_m * 32 + mi * 16 + h * 8 + g;
            float p = 0.f;
#pragma unroll
            for (int ni = 0; ni < 8; ++ni) {
                int col = warp_n * 64 + ni * 8 + 2 * tg;
                float kc0 = __bfloat162float(smA[row * 136 + col]);
                float kc1 = __bfloat162float(smA[row * 136 + col + 1]);
                p = fmaf(acc[mi][ni][2 * h + 0], kc0, p);
                p = fmaf(acc[mi][ni][2 * h + 1], kc1, p);
            }
            atomicAdd(&s_acc[row], p);
        }
    __syncthreads();
    if (t < 128) g_ksq[k0 + t] = s_acc[t];
}

// ---------------- kernel 5: main fused distance kernel ----------------------
__global__ __launch_bounds__(256) void dist_kernel(float* __restrict__ out) {
    extern __shared__ char smem[];
    float* s_qsq = (float*)(smem + 69632);
    float* s_ksq = (float*)(smem + 70144);
    int t = threadIdx.x;
    int kt = blockIdx.x, qt = blockIdx.y, b = blockIdx.z;
    int q0 = qt * 128, k0 = kt * 128;

    const uint4* gA = (const uint4*)(g_qp + (size_t)(b * LQ + q0) * DC);
    const uint4* gB = (const uint4*)(g_kc + (size_t)(b * LK + k0) * DC);
    uint4* sA4 = (uint4*)smem;
    uint4* sB4 = (uint4*)(smem + 34816);
#pragma unroll
    for (int i = t; i < 2048; i += 256) {
        int r = i >> 4, ch = i & 15;
        sA4[r * 17 + ch] = gA[i];
        sB4[r * 17 + ch] = gB[i];
    }
    if (t < 128) {
        s_qsq[t] = g_qsq[b * LQ + q0 + t];
        s_ksq[t] = g_ksq[b * LK + k0 + t];
    }
    __syncthreads();

    int lane = t & 31, wid = t >> 5;
    int warp_m = wid & 3, warp_n = wid >> 2;
    float acc[2][8][4];
#pragma unroll
    for (int mi = 0; mi < 2; ++mi)
#pragma unroll
        for (int ni = 0; ni < 8; ++ni)
#pragma unroll
            for (int e = 0; e < 4; ++e) acc[mi][ni][e] = 0.f;

    uint32_t smA_u = (uint32_t)__cvta_generic_to_shared(smem);
    uint32_t smB_u = (uint32_t)__cvta_generic_to_shared(smem + 34816);
    block_mma_128(smA_u, smB_u, lane, warp_m, warp_n, acc);

    int g = lane >> 2, tg = lane & 3;
    float qs_r[4], eq_r[4];
#pragma unroll
    for (int mi = 0; mi < 2; ++mi)
#pragma unroll
        for (int h = 0; h < 2; ++h) {
            int row = warp_m * 32 + mi * 16 + h * 8 + g;
            float qs = s_qsq[row];
            qs_r[mi * 2 + h] = qs;
            eq_r[mi * 2 + h] = 1.0f - fminf(qs, 1.0f - EPS);
        }

    const float LN2 = 0.69314718056f;
#pragma unroll
    for (int ni = 0; ni < 8; ++ni) {
        int col = warp_n * 64 + ni * 8 + 2 * tg;
        float ks0 = s_ksq[col], ks1 = s_ksq[col + 1];
        float ek0 = 1.0f - fminf(ks0, 1.0f - EPS);
        float ek1 = 1.0f - fminf(ks1, 1.0f - EPS);
#pragma unroll
        for (int mi = 0; mi < 2; ++mi)
#pragma unroll
            for (int h = 0; h < 2; ++h) {
                float qs = qs_r[mi * 2 + h], eq = eq_r[mi * 2 + h];
                float qk0 = acc[mi][ni][2 * h + 0];
                float qk1 = acc[mi][ni][2 * h + 1];
                float d0 = fmaxf(qs + ks0 - 2.0f * qk0, 0.0f);
                float d1 = fmaxf(qs + ks1 - 2.0f * qk1, 0.0f);
                float den0 = fmaf(eq, ek0, EPS);
                float den1 = fmaf(eq, ek1, EPS);
                float r0, r1;
                // Fast path: t = 2*diff/denom >= 1e4  ->  acosh(1+t) = ln2*(2+log2(diff)-log2(denom))
                if (d0 > 5.0e3f * den0)
                    r0 = LN2 * (2.0f + __log2f(d0) - __log2f(den0));
                else
                    r0 = acoshf(1.0f + 2.0f * d0 / den0);
                if (d1 > 5.0e3f * den1)
                    r1 = LN2 * (2.0f + __log2f(d1) - __log2f(den1));
                else
                    r1 = acoshf(1.0f + 2.0f * d1 / den1);
                int row = warp_m * 32 + mi * 16 + h * 8 + g;
                float2 wv = make_float2(r0, r1);
                *(float2*)(out + (size_t)(b * LQ + q0 + row) * LK + k0 + col) = wv;
            }
    }
}

// ---------------- launch ----------------------------------------------------
extern "C" void kernel_launch(void* const* d_in, const int* in_sizes, int n_in,
                              void* d_out, int out_size) {
    (void)in_sizes; (void)n_in; (void)out_size;
    const float* q   = (const float*)d_in[0];
    const int*   kq  = (const int*)d_in[1];
    const float* ksc = (const float*)d_in[2];
    const float* kzp = (const float*)d_in[3];
    const float* W   = (const float*)d_in[4];
    float* out = (float*)d_out;

    const int SMEM = 70656;  // 2x (128x136 bf16) tiles + 2x float[128]
    cudaFuncSetAttribute(ksq_kernel,  cudaFuncAttributeMaxDynamicSharedMemorySize, SMEM);
    cudaFuncSetAttribute(dist_kernel, cudaFuncAttributeMaxDynamicSharedMemorySize, SMEM);

    g_kernel<<<128, 128>>>(W);
    qp_kernel<<<(B_ * LQ) / 8, 256>>>(q, W);
    deq_kernel<<<(B_ * LK * DC) / 4 / 256, 256>>>(kq, ksc, kzp);
    ksq_kernel<<<(B_ * LK) / 128, 256, SMEM>>>();
    dist_kernel<<<dim3(LK / 128, LQ / 128, B_), 256, SMEM>>>(out);
}

// round 4
// speedup vs baseline: 1.0095x; 1.0095x over previous
#include <cuda_runtime.h>
#include <cuda_bf16.h>
#include <cstdint>
#include <math.h>

#define EPS 1e-6f
#define B_  8
#define LQ  1024
#define LK  8192
#define D_  256
#define DC  128

// ---------------- scratch (device globals; no allocations allowed) ----------
__device__ __nv_bfloat16 g_qp[B_ * LQ * DC];   // q' = q @ W_up  (bf16)      2 MB
__device__ float         g_qsq[B_ * LQ];       // ||q||^2 (fp32)
__device__ __nv_bfloat16 g_kc[B_ * LK * DC];   // dequantized k_c (bf16)    16 MB
__device__ float         g_ksq[B_ * LK];       // ||k||^2 via Gram form
__device__ __nv_bfloat16 g_G[DC * DC];         // G = W^T W (bf16)

// ---------------- kernel 1: Gram matrix G = W^T W ---------------------------
__global__ void g_kernel(const float* __restrict__ W) {
    int c1 = blockIdx.x, c2 = threadIdx.x;
    float acc = 0.f;
#pragma unroll 8
    for (int d = 0; d < D_; ++d)
        acc = fmaf(__ldg(W + d * DC + c1), __ldg(W + d * DC + c2), acc);
    g_G[c1 * DC + c2] = __float2bfloat16(acc);
}

// ---------------- kernel 2: q' = q @ W_up (bf16) and q_sq -------------------
__global__ __launch_bounds__(256) void qp_kernel(const float* __restrict__ q,
                                                 const float* __restrict__ W) {
    __shared__ float qs[8 * 256];
    int t = threadIdx.x;
    size_t base = (size_t)blockIdx.x * 2048;  // 8 rows x 256
#pragma unroll
    for (int i = t; i < 2048; i += 256) qs[i] = q[base + i];
    __syncthreads();

    int lane = t & 31, w = t >> 5;
    // q_sq: warp w reduces row w
    float s = 0.f;
#pragma unroll
    for (int i = 0; i < 8; ++i) {
        float v = qs[w * 256 + lane + i * 32];
        s = fmaf(v, v, s);
    }
#pragma unroll
    for (int o = 16; o; o >>= 1) s += __shfl_xor_sync(0xffffffffu, s, o);
    if (lane == 0) g_qsq[blockIdx.x * 8 + w] = s;

    // q': thread (w, lane) computes cols 4*lane..4*lane+3 of row w
    const float4* W4 = (const float4*)W;
    float ax = 0.f, ay = 0.f, az = 0.f, aw = 0.f;
#pragma unroll 4
    for (int d = 0; d < D_; ++d) {
        float qv = qs[w * 256 + d];
        float4 ww = W4[d * 32 + lane];
        ax = fmaf(qv, ww.x, ax);
        ay = fmaf(qv, ww.y, ay);
        az = fmaf(qv, ww.z, az);
        aw = fmaf(qv, ww.w, aw);
    }
    __nv_bfloat162 p01 = __floats2bfloat162_rn(ax, ay);
    __nv_bfloat162 p23 = __floats2bfloat162_rn(az, aw);
    uint2 wv = make_uint2(*reinterpret_cast<unsigned int*>(&p01),
                          *reinterpret_cast<unsigned int*>(&p23));
    ((uint2*)g_qp)[(blockIdx.x * 8 + w) * 32 + lane] = wv;
}

// ---------------- kernel 3: int4-code dequant -> bf16 -----------------------
__global__ void deq_kernel(const int* __restrict__ kq,
                           const float* __restrict__ sc,
                           const float* __restrict__ zp) {
    int i = blockIdx.x * 256 + threadIdx.x;  // item of 4 elements
    int4 v = ((const int4*)kq)[i];
    int flat = i << 2;
    int c = flat & (DC - 1);
    int b = flat >> 20;  // 8192*128 = 2^20 elems per batch
    float4 s = *(const float4*)(sc + b * DC + c);
    float4 z = *(const float4*)(zp + b * DC + c);
    float f0 = s.x * ((float)v.x - z.x);
    float f1 = s.y * ((float)v.y - z.y);
    float f2 = s.z * ((float)v.z - z.z);
    float f3 = s.w * ((float)v.w - z.w);
    __nv_bfloat162 p01 = __floats2bfloat162_rn(f0, f1);
    __nv_bfloat162 p23 = __floats2bfloat162_rn(f2, f3);
    uint2 wv = make_uint2(*reinterpret_cast<unsigned int*>(&p01),
                          *reinterpret_cast<unsigned int*>(&p23));
    ((uint2*)g_kc)[i] = wv;
}

// ---------------- shared 128x128x128 bf16 block-MMA (mma.sync) --------------
// Tiles in smem with padded stride 136 bf16 (272 B) -> conflict-free ldmatrix.
// acc[mi][ni][e]: warp tile 32(M) x 64(N); warps 4(M) x 2(N).
__device__ __forceinline__ void block_mma_128(uint32_t smA, uint32_t smB,
                                              int lane, int warp_m, int warp_n,
                                              float acc[2][8][4]) {
    const int STRIDE = 272;
#pragma unroll
    for (int kk = 0; kk < 8; ++kk) {
        uint32_t a[2][4];
#pragma unroll
        for (int mi = 0; mi < 2; ++mi) {
            int row = warp_m * 32 + mi * 16 + (lane & 15);
            uint32_t addr = smA + row * STRIDE + kk * 32 + ((lane >> 4) << 4);
            asm volatile("ldmatrix.sync.aligned.m8n8.x4.shared.b16 {%0,%1,%2,%3}, [%4];"
                         : "=r"(a[mi][0]), "=r"(a[mi][1]), "=r"(a[mi][2]), "=r"(a[mi][3])
                         : "r"(addr));
        }
        uint32_t bb[8][2];
#pragma unroll
        for (int nn = 0; nn < 4; ++nn) {
            int nrow = warp_n * 64 + nn * 16 + (lane & 7) + (((lane >> 4) & 1) << 3);
            uint32_t addr = smB + nrow * STRIDE + kk * 32 + (((lane >> 3) & 1) << 4);
            uint32_t r0, r1, r2, r3;
            asm volatile("ldmatrix.sync.aligned.m8n8.x4.shared.b16 {%0,%1,%2,%3}, [%4];"
                         : "=r"(r0), "=r"(r1), "=r"(r2), "=r"(r3)
                         : "r"(addr));
            bb[2 * nn][0] = r0; bb[2 * nn][1] = r1;
            bb[2 * nn + 1][0] = r2; bb[2 * nn + 1][1] = r3;
        }
#pragma unroll
        for (int mi = 0; mi < 2; ++mi)
#pragma unroll
            for (int ni = 0; ni < 8; ++ni)
                asm volatile(
                    "mma.sync.aligned.m16n8k16.row.col.f32.bf16.bf16.f32 "
                    "{%0,%1,%2,%3}, {%4,%5,%6,%7}, {%8,%9}, {%0,%1,%2,%3};"
                    : "+f"(acc[mi][ni][0]), "+f"(acc[mi][ni][1]),
                      "+f"(acc[mi][ni][2]), "+f"(acc[mi][ni][3])
                    : "r"(a[mi][0]), "r"(a[mi][1]), "r"(a[mi][2]), "r"(a[mi][3]),
                      "r"(bb[ni][0]), "r"(bb[ni][1]));
    }
}

// ---------------- kernel 4: k_sq via Gram quadratic form --------------------
__global__ __launch_bounds__(256) void ksq_kernel() {
    extern __shared__ char smem[];
    __nv_bfloat16* smA = (__nv_bfloat16*)smem;             // kc tile 128x136
    float* s_acc = (float*)(smem + 69632);
    int t = threadIdx.x;
    int k0 = blockIdx.x * 128;  // flat row over B_*LK

    const uint4* gA = (const uint4*)(g_kc + (size_t)k0 * DC);
    const uint4* gB = (const uint4*)g_G;
    uint4* sA4 = (uint4*)smem;
    uint4* sB4 = (uint4*)(smem + 34816);
#pragma unroll
    for (int i = t; i < 2048; i += 256) {
        int r = i >> 4, ch = i & 15;
        sA4[r * 17 + ch] = gA[i];
        sB4[r * 17 + ch] = gB[i];
    }
    if (t < 128) s_acc[t] = 0.f;
    __syncthreads();

    int lane = t & 31, wid = t >> 5;
    int warp_m = wid & 3, warp_n = wid >> 2;
    float acc[2][8][4];
#pragma unroll
    for (int mi = 0; mi < 2; ++mi)
#pragma unroll
        for (int ni = 0; ni < 8; ++ni)
#pragma unroll
            for (int e = 0; e < 4; ++e) acc[mi][ni][e] = 0.f;

    uint32_t smA_u = (uint32_t)__cvta_generic_to_shared(smem);
    uint32_t smB_u = (uint32_t)__cvta_generic_to_shared(smem + 34816);
    block_mma_128(smA_u, smB_u, lane, warp_m, warp_n, acc);

    int g = lane >> 2, tg = lane & 3;
#pragma unroll
    for (int mi = 0; mi < 2; ++mi)
#pragma unroll
        for (int h = 0; h < 2; ++h) {
            int row = warp_m * 32 + mi * 16 + h * 8 + g;
            float p = 0.f;
#pragma unroll
            for (int ni = 0; ni < 8; ++ni) {
                int col = warp_n * 64 + ni * 8 + 2 * tg;
                float kc0 = __bfloat162float(smA[row * 136 + col]);
                float kc1 = __bfloat162float(smA[row * 136 + col + 1]);
                p = fmaf(acc[mi][ni][2 * h + 0], kc0, p);
                p = fmaf(acc[mi][ni][2 * h + 1], kc1, p);
            }
            atomicAdd(&s_acc[row], p);
        }
    __syncthreads();
    if (t < 128) g_ksq[k0 + t] = s_acc[t];
}

// ---------------- kernel 5: main fused distance kernel ----------------------
__global__ __launch_bounds__(256) void dist_kernel(float* __restrict__ out) {
    extern __shared__ char smem[];
    float* s_qsq = (float*)(smem + 69632);
    float* s_ksq = (float*)(smem + 70144);
    int t = threadIdx.x;
    int kt = blockIdx.x, qt = blockIdx.y, b = blockIdx.z;
    int q0 = qt * 128, k0 = kt * 128;

    const uint4* gA = (const uint4*)(g_qp + (size_t)(b * LQ + q0) * DC);
    const uint4* gB = (const uint4*)(g_kc + (size_t)(b * LK + k0) * DC);
    uint4* sA4 = (uint4*)smem;
    uint4* sB4 = (uint4*)(smem + 34816);
#pragma unroll
    for (int i = t; i < 2048; i += 256) {
        int r = i >> 4, ch = i & 15;
        sA4[r * 17 + ch] = gA[i];
        sB4[r * 17 + ch] = gB[i];
    }
    if (t < 128) {
        s_qsq[t] = g_qsq[b * LQ + q0 + t];
        s_ksq[t] = g_ksq[b * LK + k0 + t];
    }
    __syncthreads();

    int lane = t & 31, wid = t >> 5;
    int warp_m = wid & 3, warp_n = wid >> 2;
    float acc[2][8][4];
#pragma unroll
    for (int mi = 0; mi < 2; ++mi)
#pragma unroll
        for (int ni = 0; ni < 8; ++ni)
#pragma unroll
            for (int e = 0; e < 4; ++e) acc[mi][ni][e] = 0.f;

    uint32_t smA_u = (uint32_t)__cvta_generic_to_shared(smem);
    uint32_t smB_u = (uint32_t)__cvta_generic_to_shared(smem + 34816);
    block_mma_128(smA_u, smB_u, lane, warp_m, warp_n, acc);

    int g = lane >> 2, tg = lane & 3;
    float qs_r[4], eq_r[4];
#pragma unroll
    for (int mi = 0; mi < 2; ++mi)
#pragma unroll
        for (int h = 0; h < 2; ++h) {
            int row = warp_m * 32 + mi * 16 + h * 8 + g;
            float qs = s_qsq[row];
            qs_r[mi * 2 + h] = qs;
            eq_r[mi * 2 + h] = 1.0f - fminf(qs, 1.0f - EPS);
        }

    const float LN2 = 0.69314718056f;
#pragma unroll
    for (int ni = 0; ni < 8; ++ni) {
        int col = warp_n * 64 + ni * 8 + 2 * tg;
        float ks0 = s_ksq[col], ks1 = s_ksq[col + 1];
        float ek0 = 1.0f - fminf(ks0, 1.0f - EPS);
        float ek1 = 1.0f - fminf(ks1, 1.0f - EPS);
#pragma unroll
        for (int mi = 0; mi < 2; ++mi)
#pragma unroll
            for (int h = 0; h < 2; ++h) {
                float qs = qs_r[mi * 2 + h], eq = eq_r[mi * 2 + h];
                float qk0 = acc[mi][ni][2 * h + 0];
                float qk1 = acc[mi][ni][2 * h + 1];
                float d0 = fmaxf(qs + ks0 - 2.0f * qk0, 0.0f);
                float d1 = fmaxf(qs + ks1 - 2.0f * qk1, 0.0f);
                float den0 = fmaf(eq, ek0, EPS);
                float den1 = fmaf(eq, ek1, EPS);
                float r0, r1;
                // Fast path: t = 2*diff/denom >= 1e4  ->  acosh(1+t) = ln2*(2+log2(diff)-log2(denom))
                if (d0 > 5.0e3f * den0)
                    r0 = LN2 * (2.0f + __log2f(d0) - __log2f(den0));
                else
                    r0 = acoshf(1.0f + 2.0f * d0 / den0);
                if (d1 > 5.0e3f * den1)
                    r1 = LN2 * (2.0f + __log2f(d1) - __log2f(den1));
                else
                    r1 = acoshf(1.0f + 2.0f * d1 / den1);
                int row = warp_m * 32 + mi * 16 + h * 8 + g;
                float2 wv = make_float2(r0, r1);
                *(float2*)(out + (size_t)(b * LQ + q0 + row) * LK + k0 + col) = wv;
            }
    }
}

// ---------------- launch ----------------------------------------------------
extern "C" void kernel_launch(void* const* d_in, const int* in_sizes, int n_in,
                              void* d_out, int out_size) {
    (void)in_sizes; (void)n_in; (void)out_size;
    const float* q   = (const float*)d_in[0];
    const int*   kq  = (const int*)d_in[1];
    const float* ksc = (const float*)d_in[2];
    const float* kzp = (const float*)d_in[3];
    const float* W   = (const float*)d_in[4];
    float* out = (float*)d_out;

    const int SMEM = 70656;  // 2x (128x136 bf16) tiles + 2x float[128]
    cudaFuncSetAttribute(ksq_kernel,  cudaFuncAttributeMaxDynamicSharedMemorySize, SMEM);
    cudaFuncSetAttribute(dist_kernel, cudaFuncAttributeMaxDynamicSharedMemorySize, SMEM);

    g_kernel<<<128, 128>>>(W);
    qp_kernel<<<(B_ * LQ) / 8, 256>>>(q, W);
    deq_kernel<<<(B_ * LK * DC) / 4 / 256, 256>>>(kq, ksc, kzp);
    ksq_kernel<<<(B_ * LK) / 128, 256, SMEM>>>();
    dist_kernel<<<dim3(LK / 128, LQ / 128, B_), 256, SMEM>>>(out);
}